// round 1
// baseline (speedup 1.0000x reference)
#include <cuda_runtime.h>
#include <cstdint>
#include <cstddef>

#define HID        256
#define NNODES     50000
#define NEDGES     800000
#define NROWS_LBL  8192   // 4096 pairs * 2

// Scratch (allocation-free rule: __device__ globals)
__device__ float g_x0[(size_t)NNODES * HID];
__device__ float g_h [(size_t)NNODES * HID];
__device__ float g_x [(size_t)NNODES * HID];

// C[row] = A[row] @ W + bias   (K = N = 256 fixed)
// If rowmap != nullptr: row -> rowmap[row] on BOTH the A gather and C scatter
// (implements x0[idx] = x[idx] @ f1_w + f1_b).
__global__ __launch_bounds__(256)
void gemm_bias(const float* __restrict__ A, const float* __restrict__ W,
               const float* __restrict__ bias, float* __restrict__ C,
               int M, const int* __restrict__ rowmap)
{
    __shared__ float As[16][128];   // As[k][m]
    __shared__ float Bs[16][128];   // Bs[k][n]

    const int tid = threadIdx.x;
    const int bm  = blockIdx.x * 128;
    const int bn  = blockIdx.y * 128;
    const int tx  = tid & 15;       // n-tile 8 cols
    const int ty  = tid >> 4;       // m-tile 8 rows

    float acc[8][8];
#pragma unroll
    for (int i = 0; i < 8; i++)
#pragma unroll
        for (int j = 0; j < 8; j++) acc[i][j] = 0.f;

    // A rows this thread loads (2 float4 loads per K-step)
    int arow[2];
#pragma unroll
    for (int i = 0; i < 2; i++) {
        int idx = i * 256 + tid;          // 0..511
        int r   = idx >> 2;               // 0..127
        int row = bm + r;
        if (rowmap)          row = __ldg(&rowmap[row]);
        else if (row >= M)   row = -1;
        arow[i] = row;
    }

    for (int k0 = 0; k0 < HID; k0 += 16) {
        // A tile: 128 rows x 16 k, stored transposed
#pragma unroll
        for (int i = 0; i < 2; i++) {
            int idx = i * 256 + tid;
            int r   = idx >> 2;
            int c   = (idx & 3) << 2;     // 0,4,8,12
            float4 v = make_float4(0.f, 0.f, 0.f, 0.f);
            if (arow[i] >= 0)
                v = *(const float4*)(A + (size_t)arow[i] * HID + k0 + c);
            As[c + 0][r] = v.x; As[c + 1][r] = v.y;
            As[c + 2][r] = v.z; As[c + 3][r] = v.w;
        }
        // B tile: 16 k x 128 n, coalesced float4
#pragma unroll
        for (int i = 0; i < 2; i++) {
            int idx = i * 256 + tid;
            int kk  = idx >> 5;           // 0..15
            int n4  = (idx & 31) << 2;    // 0..124
            *(float4*)&Bs[kk][n4] =
                *(const float4*)(W + (size_t)(k0 + kk) * HID + bn + n4);
        }
        __syncthreads();

#pragma unroll
        for (int k = 0; k < 16; k++) {
            float a[8], b[8];
#pragma unroll
            for (int i = 0; i < 8; i++) a[i] = As[k][ty * 8 + i];
#pragma unroll
            for (int j = 0; j < 8; j++) b[j] = Bs[k][tx * 8 + j];
#pragma unroll
            for (int i = 0; i < 8; i++)
#pragma unroll
                for (int j = 0; j < 8; j++)
                    acc[i][j] = fmaf(a[i], b[j], acc[i][j]);
        }
        __syncthreads();
    }

    // Epilogue: + bias, store (scatter via rowmap if present)
#pragma unroll
    for (int i = 0; i < 8; i++) {
        int row = bm + ty * 8 + i;
        if (rowmap)        row = __ldg(&rowmap[row]);
        else if (row >= M) continue;
#pragma unroll
        for (int j = 0; j < 8; j += 4) {
            int col = bn + tx * 8 + j;
            float4 v;
            v.x = acc[i][j + 0] + bias[col + 0];
            v.y = acc[i][j + 1] + bias[col + 1];
            v.z = acc[i][j + 2] + bias[col + 2];
            v.w = acc[i][j + 3] + bias[col + 3];
            *(float4*)(C + (size_t)row * HID + col) = v;
        }
    }
}

__global__ void zero_kernel(float4* __restrict__ p, int n4)
{
    int t = blockIdx.x * blockDim.x + threadIdx.x;
    if (t < n4) p[t] = make_float4(0.f, 0.f, 0.f, 0.f);
}

// out[dst[e]] += h[src[e]]  — one warp per edge, v4 reductions (no return).
__global__ __launch_bounds__(256)
void edge_scatter(const float* __restrict__ h, const int* __restrict__ src,
                  const int* __restrict__ dst, float* __restrict__ out)
{
    int gw   = (int)((blockIdx.x * (unsigned)blockDim.x + threadIdx.x) >> 5);
    int lane = threadIdx.x & 31;
    if (gw >= NEDGES) return;
    int s = __ldg(&src[gw]);
    int d = __ldg(&dst[gw]);
    const float4* hrow = (const float4*)(h + (size_t)s * HID);
    float*        orow = out + (size_t)d * HID;
#pragma unroll
    for (int j = 0; j < 2; j++) {
        int c = j * 32 + lane;            // float4 index 0..63
        float4 v = __ldg(&hrow[c]);
        asm volatile("red.global.add.v4.f32 [%0], {%1,%2,%3,%4};"
                     :: "l"(orow + c * 4),
                        "f"(v.x), "f"(v.y), "f"(v.z), "f"(v.w)
                     : "memory");
    }
}

__global__ void gather_out(const float* __restrict__ x, const int* __restrict__ pos,
                           float4* __restrict__ out)
{
    int t = blockIdx.x * blockDim.x + threadIdx.x;
    if (t >= NROWS_LBL * 64) return;
    int r   = t >> 6;
    int c   = t & 63;
    int row = __ldg(&pos[r]);
    out[t] = *(const float4*)(x + (size_t)row * HID + (c << 2));
}

extern "C" void kernel_launch(void* const* d_in, const int* in_sizes, int n_in,
                              void* d_out, int out_size)
{
    (void)in_sizes; (void)n_in; (void)out_size;
    const float* x    = (const float*)d_in[0];
    const float* f0w  = (const float*)d_in[1];
    const float* f0b  = (const float*)d_in[2];
    const float* f1w  = (const float*)d_in[3];
    const float* f1b  = (const float*)d_in[4];
    const float* cw   = (const float*)d_in[5];
    const float* cb   = (const float*)d_in[6];
    const int*   esrc = (const int*)d_in[7];
    const int*   edst = (const int*)d_in[8];
    const int*   pos  = (const int*)d_in[9];  // flattened (4096,2) -> 8192 row ids

    float *x0, *h, *xc;
    cudaGetSymbolAddress((void**)&x0, g_x0);
    cudaGetSymbolAddress((void**)&h,  g_h);
    cudaGetSymbolAddress((void**)&xc, g_x);

    dim3 blk(256);
    dim3 gN((NNODES + 127) / 128, 2);
    dim3 gL(NROWS_LBL / 128, 2);

    const int n4 = NNODES * HID / 4;
    const int scatter_blocks = (int)(((long long)NEDGES * 32 + 255) / 256);

    const float* xin = x;
    for (int i = 0; i < 3; i++) {
        const size_t wo = (size_t)i * HID * HID;
        // x0 = xin @ f0_w[i] + f0_b[i]
        gemm_bias<<<gN, blk>>>(xin, f0w + wo, f0b + i * HID, x0, NNODES, nullptr);
        // x0[idx] = xin[idx] @ f1_w[i] + f1_b[i]
        gemm_bias<<<gL, blk>>>(xin, f1w + wo, f1b + i * HID, x0, NROWS_LBL, pos);
        // h = x0 @ conv_w[i] + conv_b[i]
        gemm_bias<<<gN, blk>>>(x0, cw + wo, cb + i * HID, h, NNODES, nullptr);
        // x = segment_sum(h[src], dst)
        zero_kernel<<<(n4 + 255) / 256, 256>>>((float4*)xc, n4);
        edge_scatter<<<scatter_blocks, 256>>>(h, esrc, edst, xc);
        xin = xc;
    }
    gather_out<<<(NROWS_LBL * 64 + 255) / 256, 256>>>(xc, pos, (float4*)d_out);
}

// round 3
// speedup vs baseline: 1.5397x; 1.5397x over previous
#include <cuda_runtime.h>
#include <cuda_bf16.h>
#include <cstdint>
#include <cstddef>

#define HID        256
#define NNODES     50000
#define NEDGES     800000
#define NROWS_LBL  8192

// ---------------- scratch (allocation-free rule) ----------------
__device__ float g_x0[(size_t)NNODES * HID];
__device__ float g_h [(size_t)NNODES * HID];
__device__ float g_x [(size_t)NNODES * HID];
__device__ __nv_bfloat16 g_xh[(size_t)NNODES * HID];
__device__ __nv_bfloat16 g_xl[(size_t)NNODES * HID];
__device__ __nv_bfloat16 g_wth[9 * 65536];   // transposed weights [n][k], hi
__device__ __nv_bfloat16 g_wtl[9 * 65536];   // transposed weights [n][k], lo

// ---------------- mma.sync bf16 split GEMM ----------------
// C[row, bn:bn+128] = (Ah+Al)[row, :] @ (Wth+Wtl)[bn:bn+128, :]^T + bias
// CTA: 128 (M) x 128 (N), 8 warps in 2x4, warp tile 64x32.
#define KC      32          // K chunk in SMEM
#define LDS_A   40          // padded row stride (halves): 80B = 20 banks -> conflict-free
#define LDS_B   40

__device__ __forceinline__ void mma16816(float* c, const uint32_t* a, const uint32_t* b)
{
    asm volatile(
        "mma.sync.aligned.m16n8k16.row.col.f32.bf16.bf16.f32 "
        "{%0,%1,%2,%3}, {%4,%5,%6,%7}, {%8,%9}, {%0,%1,%2,%3};"
        : "+f"(c[0]), "+f"(c[1]), "+f"(c[2]), "+f"(c[3])
        : "r"(a[0]), "r"(a[1]), "r"(a[2]), "r"(a[3]), "r"(b[0]), "r"(b[1]));
}

__global__ __launch_bounds__(256, 2)
void tc_gemm(const __nv_bfloat16* __restrict__ Ah, const __nv_bfloat16* __restrict__ Al,
             const __nv_bfloat16* __restrict__ Wth, const __nv_bfloat16* __restrict__ Wtl,
             const float* __restrict__ bias, float* __restrict__ C,
             int M, const int* __restrict__ rowmap)
{
    __shared__ __nv_bfloat16 sAh[128 * LDS_A];
    __shared__ __nv_bfloat16 sAl[128 * LDS_A];
    __shared__ __nv_bfloat16 sBh[128 * LDS_B];
    __shared__ __nv_bfloat16 sBl[128 * LDS_B];

    const int tid  = threadIdx.x;
    const int wid  = tid >> 5;
    const int lane = tid & 31;
    const int bm   = blockIdx.x * 128;
    const int bn   = blockIdx.y * 128;
    const int wr   = wid & 1;          // warp row (0..1) -> 64 rows
    const int wc   = wid >> 1;         // warp col (0..3) -> 32 cols

    const int qp = lane >> 2;          // t/4   (0..7)
    const int qr = lane & 3;           // t%4   (0..3)

    float acc[4][4][4];
#pragma unroll
    for (int i = 0; i < 4; i++)
#pragma unroll
        for (int j = 0; j < 4; j++)
#pragma unroll
            for (int r = 0; r < 4; r++) acc[i][j][r] = 0.f;

    // Rows this thread loads into the A tile (2 uint4 loads per chunk)
    int arow[2];
#pragma unroll
    for (int i = 0; i < 2; i++) {
        int u = i * 256 + tid;          // 0..511
        int r = u >> 2;                 // 0..127
        int grow = bm + r;
        arow[i] = rowmap ? __ldg(&rowmap[grow]) : (grow < M ? grow : -1);
    }

    for (int k0 = 0; k0 < HID; k0 += KC) {
        // ---- stage A (128 rows x 32 k) hi+lo ----
#pragma unroll
        for (int i = 0; i < 2; i++) {
            int u = i * 256 + tid;
            int r = u >> 2;
            int c = (u & 3) * 8;        // 0,8,16,24 halves
            uint4 vh = make_uint4(0u, 0u, 0u, 0u), vl = vh;
            if (arow[i] >= 0) {
                vh = *(const uint4*)(Ah + (size_t)arow[i] * HID + k0 + c);
                vl = *(const uint4*)(Al + (size_t)arow[i] * HID + k0 + c);
            }
            *(uint4*)(sAh + r * LDS_A + c) = vh;
            *(uint4*)(sAl + r * LDS_A + c) = vl;
        }
        // ---- stage B (128 n-rows x 32 k) hi+lo ----
#pragma unroll
        for (int i = 0; i < 2; i++) {
            int u = i * 256 + tid;
            int r = u >> 2;
            int c = (u & 3) * 8;
            *(uint4*)(sBh + r * LDS_B + c) =
                *(const uint4*)(Wth + (size_t)(bn + r) * HID + k0 + c);
            *(uint4*)(sBl + r * LDS_B + c) =
                *(const uint4*)(Wtl + (size_t)(bn + r) * HID + k0 + c);
        }
        __syncthreads();

#pragma unroll
        for (int ks = 0; ks < KC; ks += 16) {
            // A fragments: hi and lo, 4 m-tiles each
            uint32_t fAh[4][4], fAl[4][4];
#pragma unroll
            for (int mt = 0; mt < 4; mt++) {
                int r0 = wr * 64 + mt * 16 + qp;
                int kk = ks + qr * 2;
                const __nv_bfloat16* ph = sAh + r0 * LDS_A + kk;
                const __nv_bfloat16* pl = sAl + r0 * LDS_A + kk;
                fAh[mt][0] = *(const uint32_t*)(ph);
                fAh[mt][1] = *(const uint32_t*)(ph + 8 * LDS_A);
                fAh[mt][2] = *(const uint32_t*)(ph + 8);
                fAh[mt][3] = *(const uint32_t*)(ph + 8 * LDS_A + 8);
                fAl[mt][0] = *(const uint32_t*)(pl);
                fAl[mt][1] = *(const uint32_t*)(pl + 8 * LDS_A);
                fAl[mt][2] = *(const uint32_t*)(pl + 8);
                fAl[mt][3] = *(const uint32_t*)(pl + 8 * LDS_A + 8);
            }
            // B hi fragments: Ah*Bh and Al*Bh
            {
                uint32_t fB[4][2];
#pragma unroll
                for (int nt = 0; nt < 4; nt++) {
                    int n0 = wc * 32 + nt * 8 + qp;
                    int kk = ks + qr * 2;
                    const __nv_bfloat16* pb = sBh + n0 * LDS_B + kk;
                    fB[nt][0] = *(const uint32_t*)(pb);
                    fB[nt][1] = *(const uint32_t*)(pb + 8);
                }
#pragma unroll
                for (int mt = 0; mt < 4; mt++)
#pragma unroll
                    for (int nt = 0; nt < 4; nt++) {
                        mma16816(acc[mt][nt], fAh[mt], fB[nt]);
                        mma16816(acc[mt][nt], fAl[mt], fB[nt]);
                    }
            }
            // B lo fragments: Ah*Bl
            {
                uint32_t fB[4][2];
#pragma unroll
                for (int nt = 0; nt < 4; nt++) {
                    int n0 = wc * 32 + nt * 8 + qp;
                    int kk = ks + qr * 2;
                    const __nv_bfloat16* pb = sBl + n0 * LDS_B + kk;
                    fB[nt][0] = *(const uint32_t*)(pb);
                    fB[nt][1] = *(const uint32_t*)(pb + 8);
                }
#pragma unroll
                for (int mt = 0; mt < 4; mt++)
#pragma unroll
                    for (int nt = 0; nt < 4; nt++)
                        mma16816(acc[mt][nt], fAh[mt], fB[nt]);
            }
        }
        __syncthreads();
    }

    // ---- epilogue ----
#pragma unroll
    for (int mt = 0; mt < 4; mt++) {
        int grow0 = bm + wr * 64 + mt * 16 + qp;
        int grow1 = grow0 + 8;
        int row0 = rowmap ? __ldg(&rowmap[grow0]) : grow0;
        int row1 = rowmap ? __ldg(&rowmap[grow1]) : grow1;
        bool v0 = rowmap ? true : (grow0 < M);
        bool v1 = rowmap ? true : (grow1 < M);
#pragma unroll
        for (int nt = 0; nt < 4; nt++) {
            int col = bn + wc * 32 + nt * 8 + qr * 2;
            float b0 = __ldg(&bias[col]);
            float b1 = __ldg(&bias[col + 1]);
            if (v0) {
                float2 o = make_float2(acc[mt][nt][0] + b0, acc[mt][nt][1] + b1);
                *(float2*)(C + (size_t)row0 * HID + col) = o;
            }
            if (v1) {
                float2 o = make_float2(acc[mt][nt][2] + b0, acc[mt][nt][3] + b1);
                *(float2*)(C + (size_t)row1 * HID + col) = o;
            }
        }
    }
}

// ---------------- fp32 -> bf16 hi/lo pair ----------------
__global__ void to_pair(const float* __restrict__ in,
                        __nv_bfloat16* __restrict__ hi, __nv_bfloat16* __restrict__ lo,
                        int n4)
{
    int t = blockIdx.x * blockDim.x + threadIdx.x;
    if (t >= n4) return;
    float4 v = ((const float4*)in)[t];
    __nv_bfloat16 h0 = __float2bfloat16(v.x);
    __nv_bfloat16 h1 = __float2bfloat16(v.y);
    __nv_bfloat16 h2 = __float2bfloat16(v.z);
    __nv_bfloat16 h3 = __float2bfloat16(v.w);
    __nv_bfloat162 hp0 = __nv_bfloat162(h0, h1);
    __nv_bfloat162 hp1 = __nv_bfloat162(h2, h3);
    __nv_bfloat162 lp0 = __nv_bfloat162(__float2bfloat16(v.x - __bfloat162float(h0)),
                                        __float2bfloat16(v.y - __bfloat162float(h1)));
    __nv_bfloat162 lp1 = __nv_bfloat162(__float2bfloat16(v.z - __bfloat162float(h2)),
                                        __float2bfloat16(v.w - __bfloat162float(h3)));
    ((__nv_bfloat162*)hi)[t * 2 + 0] = hp0;
    ((__nv_bfloat162*)hi)[t * 2 + 1] = hp1;
    ((__nv_bfloat162*)lo)[t * 2 + 0] = lp0;
    ((__nv_bfloat162*)lo)[t * 2 + 1] = lp1;
}

// ---------------- weight transpose + split ----------------
__global__ void transpose_w(const float* __restrict__ f0w, const float* __restrict__ f1w,
                            const float* __restrict__ cw,
                            __nv_bfloat16* __restrict__ wth, __nv_bfloat16* __restrict__ wtl)
{
    __shared__ float tileS[32][33];
    const int m = blockIdx.y;                 // 0..8 : layer*3 + which
    const int layer = m / 3, which = m % 3;
    const float* src = (which == 0 ? f0w : which == 1 ? f1w : cw) + (size_t)layer * 65536;
    const int tk = (blockIdx.x & 7) * 32;
    const int tn = (blockIdx.x >> 3) * 32;
    const int tx = threadIdx.x, ty = threadIdx.y;

#pragma unroll
    for (int r = 0; r < 4; r++) {
        int k = tk + ty + r * 8;
        tileS[ty + r * 8][tx] = src[k * 256 + tn + tx];
    }
    __syncthreads();
#pragma unroll
    for (int r = 0; r < 4; r++) {
        int n = tn + ty + r * 8;
        int k = tk + tx;
        float v = tileS[tx][ty + r * 8];
        __nv_bfloat16 h = __float2bfloat16(v);
        __nv_bfloat16 l = __float2bfloat16(v - __bfloat162float(h));
        wth[(size_t)m * 65536 + n * 256 + k] = h;
        wtl[(size_t)m * 65536 + n * 256 + k] = l;
    }
}

// ---------------- zero / scatter / gather ----------------
__global__ void zero_kernel(float4* __restrict__ p, int n4)
{
    int t = blockIdx.x * blockDim.x + threadIdx.x;
    if (t < n4) p[t] = make_float4(0.f, 0.f, 0.f, 0.f);
}

__global__ __launch_bounds__(256)
void edge_scatter(const float* __restrict__ h, const int* __restrict__ src,
                  const int* __restrict__ dst, float* __restrict__ out)
{
    int gw   = (int)((blockIdx.x * (unsigned)blockDim.x + threadIdx.x) >> 5);
    int lane = threadIdx.x & 31;
    if (gw >= NEDGES) return;
    int s = __ldg(&src[gw]);
    int d = __ldg(&dst[gw]);
    const float4* hrow = (const float4*)(h + (size_t)s * HID);
    float*        orow = out + (size_t)d * HID;
#pragma unroll
    for (int j = 0; j < 2; j++) {
        int c = j * 32 + lane;
        float4 v = __ldg(&hrow[c]);
        asm volatile("red.global.add.v4.f32 [%0], {%1,%2,%3,%4};"
                     :: "l"(orow + c * 4),
                        "f"(v.x), "f"(v.y), "f"(v.z), "f"(v.w)
                     : "memory");
    }
}

__global__ void gather_out(const float* __restrict__ x, const int* __restrict__ pos,
                           float4* __restrict__ out)
{
    int t = blockIdx.x * blockDim.x + threadIdx.x;
    if (t >= NROWS_LBL * 64) return;
    int r = t >> 6, c = t & 63;
    int row = __ldg(&pos[r]);
    out[t] = *(const float4*)(x + (size_t)row * HID + (c << 2));
}

// ---------------- launch ----------------
extern "C" void kernel_launch(void* const* d_in, const int* in_sizes, int n_in,
                              void* d_out, int out_size)
{
    (void)in_sizes; (void)n_in; (void)out_size;
    const float* x    = (const float*)d_in[0];
    const float* f0w  = (const float*)d_in[1];
    const float* f0b  = (const float*)d_in[2];
    const float* f1w  = (const float*)d_in[3];
    const float* f1b  = (const float*)d_in[4];
    const float* cw   = (const float*)d_in[5];
    const float* cb   = (const float*)d_in[6];
    const int*   esrc = (const int*)d_in[7];
    const int*   edst = (const int*)d_in[8];
    const int*   pos  = (const int*)d_in[9];

    float *x0, *h, *xc;
    __nv_bfloat16 *xh, *xl, *wth, *wtl;
    cudaGetSymbolAddress((void**)&x0,  g_x0);
    cudaGetSymbolAddress((void**)&h,   g_h);
    cudaGetSymbolAddress((void**)&xc,  g_x);
    cudaGetSymbolAddress((void**)&xh,  g_xh);
    cudaGetSymbolAddress((void**)&xl,  g_xl);
    cudaGetSymbolAddress((void**)&wth, g_wth);
    cudaGetSymbolAddress((void**)&wtl, g_wtl);

    const int n4 = NNODES * HID / 4;
    dim3 gN((NNODES + 127) / 128, 2);
    dim3 gL(NROWS_LBL / 128, 2);
    const int scatter_blocks = (int)(((long long)NEDGES * 32 + 255) / 256);

    transpose_w<<<dim3(64, 9), dim3(32, 8)>>>(f0w, f1w, cw, wth, wtl);

    const float* xin = x;
    for (int i = 0; i < 3; i++) {
        const size_t wo = (size_t)i * 3 * 65536;
        to_pair<<<(n4 + 255) / 256, 256>>>(xin, xh, xl, n4);
        tc_gemm<<<gN, 256>>>(xh, xl, wth + wo + 0 * 65536, wtl + wo + 0 * 65536,
                             f0b + i * HID, x0, NNODES, nullptr);
        tc_gemm<<<gL, 256>>>(xh, xl, wth + wo + 1 * 65536, wtl + wo + 1 * 65536,
                             f1b + i * HID, x0, NROWS_LBL, pos);
        to_pair<<<(n4 + 255) / 256, 256>>>(x0, xh, xl, n4);
        tc_gemm<<<gN, 256>>>(xh, xl, wth + wo + 2 * 65536, wtl + wo + 2 * 65536,
                             cb + i * HID, h, NNODES, nullptr);
        zero_kernel<<<(n4 + 255) / 256, 256>>>((float4*)xc, n4);
        edge_scatter<<<scatter_blocks, 256>>>(h, esrc, edst, xc);
        xin = xc;
    }
    gather_out<<<(NROWS_LBL * 64 + 255) / 256, 256>>>(xc, pos, (float4*)d_out);
}